// round 6
// baseline (speedup 1.0000x reference)
#include <cuda_runtime.h>
#include <cuda_bf16.h>
#include <math.h>
#include <stdint.h>

// Problem constants
#define BATCH   4096
#define HID     512
#define CARNUM  32
#define SEQLEN  33
#define TDEC    60
#define XROW    198
#define BH      (BATCH * HID)
#define MM      (HID * HID)

// GEMM tiling: 128x128 CTA tile, BK=64 (128B rows, SW128), 8 warps (2M x 4N)
#define BM 128
#define BN 128
#define CHUNK_K 64
#define STAGES 3
#define TILE_BYTES 16384                 // 128 rows x 128B
#define STAGE_BYTES (4 * TILE_BYTES)     // Ah, Al, Bh, Bl
#define SMEM_REQ (1024 + STAGES * STAGE_BYTES)

#define NCTA 128

#define SW128(o) ((o) ^ (((o) >> 3) & 0x70))

// ---------------- device globals ----------------------------------------------
__device__ __align__(128) __nv_bfloat16 g_Hh[2 * 2 * BH];
__device__ __align__(128) __nv_bfloat16 g_Hl[2 * 2 * BH];
__device__ __align__(128) __nv_bfloat16 g_Sh[SEQLEN * BH];
__device__ __align__(128) __nv_bfloat16 g_Sl[SEQLEN * BH];
__device__ __align__(128) __nv_bfloat16 g_Rh[BH];
__device__ __align__(128) __nv_bfloat16 g_Rl[BH];
__device__ __align__(128) __nv_bfloat16 g_Wh[9 * MM];
__device__ __align__(128) __nv_bfloat16 g_Wl[9 * MM];
__device__ float g_bias[4 * HID];
__device__ unsigned g_barctr;

struct Ptr9 { const float* p[9]; };

// ---------------- helpers -----------------------------------------------------
__device__ __forceinline__ void split_bf(float v, __nv_bfloat16& h, __nv_bfloat16& l) {
    h = __float2bfloat16(v);
    l = __float2bfloat16(v - __bfloat162float(h));
}

__device__ __forceinline__ void cp16(unsigned dst, const void* src) {
    asm volatile("cp.async.cg.shared.global [%0], [%1], 16;" :: "r"(dst), "l"(src) : "memory");
}

__device__ __forceinline__ void ldsm4(unsigned* r, unsigned addr) {
    asm volatile("ldmatrix.sync.aligned.m8n8.x4.shared.b16 {%0,%1,%2,%3}, [%4];"
                 : "=r"(r[0]), "=r"(r[1]), "=r"(r[2]), "=r"(r[3]) : "r"(addr));
}

__device__ __forceinline__ void mma16816(float* c, const unsigned* a, const unsigned* b) {
    asm volatile(
        "mma.sync.aligned.m16n8k16.row.col.f32.bf16.bf16.f32 "
        "{%0,%1,%2,%3}, {%4,%5,%6,%7}, {%8,%9}, {%0,%1,%2,%3};"
        : "+f"(c[0]), "+f"(c[1]), "+f"(c[2]), "+f"(c[3])
        : "r"(a[0]), "r"(a[1]), "r"(a[2]), "r"(a[3]), "r"(b[0]), "r"(b[1]));
}

// grid barrier: monotonic counter, release fence before arrive, L2 spin in tid0
__device__ __forceinline__ void grid_sync(unsigned target) {
    __syncthreads();
    if (threadIdx.x == 0) {
        __threadfence();
        atomicAdd(&g_barctr, 1u);
        while (*((volatile unsigned*)&g_barctr) < target) { }
    }
    __syncthreads();
}

// ---------------- prep kernels ------------------------------------------------
__global__ void wsplit_kernel(Ptr9 s, __nv_bfloat16* __restrict__ Wh,
                              __nv_bfloat16* __restrict__ Wl) {
    int m = blockIdx.y;
    int i = blockIdx.x * blockDim.x + threadIdx.x;
    float v = s.p[m][i];
    __nv_bfloat16 h, l;
    split_bf(v, h, l);
    Wh[(size_t)m * MM + i] = h;
    Wl[(size_t)m * MM + i] = l;
}

__global__ void bias_kernel(const float* __restrict__ ebih, const float* __restrict__ ebhh,
                            const float* __restrict__ dbih, const float* __restrict__ dbhh,
                            float* __restrict__ out) {
    int i = blockIdx.x * blockDim.x + threadIdx.x;
    if (i == 0) g_barctr = 0u;     // reset persistent-kernel barrier each launch
    if (i < 1024)      out[i] = ebih[i] + ebhh[i];
    else if (i < 2048) out[i] = dbih[i - 1024] + dbhh[i - 1024];
}

__global__ void zeroh_kernel(__nv_bfloat16* __restrict__ a, __nv_bfloat16* __restrict__ b, int n) {
    int i = blockIdx.x * blockDim.x + threadIdx.x;
    if (i < n) { a[i] = __float2bfloat16(0.f); b[i] = __float2bfloat16(0.f); }
}

// one block per batch row; all 33 timesteps
__global__ void embed_all_kernel(const float* __restrict__ x,
                                 const float* __restrict__ Wm, const float* __restrict__ bm,
                                 const float* __restrict__ Wv, const float* __restrict__ bv,
                                 __nv_bfloat16* __restrict__ Sh, __nv_bfloat16* __restrict__ Sl) {
    __shared__ float sx[XROW];
    int b = blockIdx.x, e = threadIdx.x;
    if (e < XROW) sx[e] = x[(size_t)b * XROW + e];
    __syncthreads();
    float wv[6], wm[6];
#pragma unroll
    for (int j = 0; j < 6; ++j) { wv[j] = Wv[e * 6 + j]; wm[j] = Wm[e * 6 + j]; }
    float bve = bv[e], bme = bm[e];
    for (int t = 0; t < CARNUM; ++t) {
        float s = bve;
#pragma unroll
        for (int j = 0; j < 6; ++j) s += sx[6 + 6 * t + j] * wv[j];
        float v = tanhf(s);
        __nv_bfloat16 h, l; split_bf(v, h, l);
        size_t idx = ((size_t)t * BATCH + b) * HID + e;
        Sh[idx] = h; Sl[idx] = l;
    }
    {
        float s = bme;
#pragma unroll
        for (int j = 0; j < 6; ++j) s += sx[j] * wm[j];
        float v = tanhf(s);
        __nv_bfloat16 h, l; split_bf(v, h, l);
        size_t idx = ((size_t)CARNUM * BATCH + b) * HID + e;
        Sh[idx] = h; Sl[idx] = l;
    }
}

// ---------------- bf16x3 HMMA GEMM step (device function, one I$ copy) --------
__device__ __noinline__ void
gemm_step(const __nv_bfloat16* A1h, const __nv_bfloat16* A1l,
          const __nv_bfloat16* A2h, const __nv_bfloat16* A2l,
          const __nv_bfloat16* B1h, const __nv_bfloat16* B1l,
          const __nv_bfloat16* B2h, const __nv_bfloat16* B2l,
          const float* bias, __nv_bfloat16* Ch, __nv_bfloat16* Cl,
          int act, int npairs, unsigned sm, int cta) {
    int tid  = threadIdx.x;
    int warp = tid >> 5;
    int lane = tid & 31;
    int wm = warp >> 2;        // 0..1  (M)
    int wn = warp & 3;         // 0..3  (N)
    int li  = lane & 7;
    int grp = lane >> 3;
    int mBase = (cta >> 2) * BM;
    int nBase = (cta & 3) * BN;
    int NT = npairs * (HID / CHUNK_K);      // 8 or 16

    float acc[4][4][4];
#pragma unroll
    for (int mt = 0; mt < 4; ++mt)
#pragma unroll
        for (int nt = 0; nt < 4; ++nt)
#pragma unroll
            for (int c = 0; c < 4; ++c) acc[mt][nt][c] = 0.f;

    auto prefetch = [&](int chunk) {
        int buf = chunk % STAGES;
        int pair = chunk >> 3;
        int k0 = (chunk & 7) * CHUNK_K;
        const __nv_bfloat16* P0 = pair ? A2h : A1h;
        const __nv_bfloat16* P1 = pair ? A2l : A1l;
        const __nv_bfloat16* P2 = pair ? B2h : B1h;
        const __nv_bfloat16* P3 = pair ? B2l : B1l;
        unsigned sb = sm + buf * STAGE_BYTES;
#pragma unroll
        for (int i = 0; i < 16; ++i) {
            int cid = tid + 256 * i;
            int arr = cid >> 10;               // 0..3
            int r   = (cid >> 3) & 127;
            int seg = cid & 7;
            const __nv_bfloat16* p = (arr == 0) ? P0 : (arr == 1) ? P1 : (arr == 2) ? P2 : P3;
            int rb = ((arr < 2) ? mBase : nBase) + r;
            const void* src = p + (size_t)rb * HID + k0 + seg * 8;
            unsigned dst = sb + arr * TILE_BYTES + SW128(r * 128 + seg * 16);
            cp16(dst, src);
        }
        asm volatile("cp.async.commit_group;" ::: "memory");
    };

    prefetch(0);
    if (NT > 1) prefetch(1);

    for (int c = 0; c < NT; ++c) {
        if (c + 2 < NT) prefetch(c + 2);
        if (c + 2 < NT)      asm volatile("cp.async.wait_group 2;" ::: "memory");
        else if (c + 1 < NT) asm volatile("cp.async.wait_group 1;" ::: "memory");
        else                 asm volatile("cp.async.wait_group 0;" ::: "memory");
        __syncthreads();

        unsigned sb  = sm + (c % STAGES) * STAGE_BYTES;
        unsigned sAh = sb;
        unsigned sAl = sb + TILE_BYTES;
        unsigned sBh = sb + 2 * TILE_BYTES;
        unsigned sBl = sb + 3 * TILE_BYTES;

#pragma unroll
        for (int kq = 0; kq < 4; ++kq) {
            unsigned ah[4][4], al_[4][4];
#pragma unroll
            for (int mt = 0; mt < 4; ++mt) {
                int r = wm * 64 + mt * 16 + ((grp & 1) << 3) + li;
                int cc = kq * 32 + ((grp & 2) << 3);
                unsigned off = (unsigned)(r * 128 + (cc ^ (li << 4)));
                ldsm4(ah[mt],  sAh + off);
                ldsm4(al_[mt], sAl + off);
            }
            unsigned bh[2][4], bl_[2][4];
#pragma unroll
            for (int nb = 0; nb < 2; ++nb) {
                int n = wn * 32 + nb * 16 + ((grp & 2) << 2) + li;
                int cc = kq * 32 + ((grp & 1) << 4);
                unsigned off = (unsigned)(n * 128 + (cc ^ (li << 4)));
                ldsm4(bh[nb],  sBh + off);
                ldsm4(bl_[nb], sBl + off);
            }
#pragma unroll
            for (int mt = 0; mt < 4; ++mt)
#pragma unroll
                for (int nt = 0; nt < 4; ++nt)
                    mma16816(acc[mt][nt], ah[mt], &bh[nt >> 1][(nt & 1) * 2]);
#pragma unroll
            for (int mt = 0; mt < 4; ++mt)
#pragma unroll
                for (int nt = 0; nt < 4; ++nt)
                    mma16816(acc[mt][nt], ah[mt], &bl_[nt >> 1][(nt & 1) * 2]);
#pragma unroll
            for (int mt = 0; mt < 4; ++mt)
#pragma unroll
                for (int nt = 0; nt < 4; ++nt)
                    mma16816(acc[mt][nt], al_[mt], &bh[nt >> 1][(nt & 1) * 2]);
        }
        __syncthreads();
    }

    // ---- epilogue: bias + activation, split to bf16 hi/lo ----
#pragma unroll
    for (int mt = 0; mt < 4; ++mt) {
        int r0 = mBase + wm * 64 + mt * 16 + (lane >> 2);
#pragma unroll
        for (int nt = 0; nt < 4; ++nt) {
            int n0 = nBase + wn * 32 + nt * 8 + 2 * (lane & 3);
            float b0 = bias[n0], b1 = bias[n0 + 1];
#pragma unroll
            for (int half = 0; half < 2; ++half) {
                int r = r0 + half * 8;
                float v0 = acc[mt][nt][half * 2 + 0] + b0;
                float v1 = acc[mt][nt][half * 2 + 1] + b1;
                if (act == 1) { v0 = tanhf(v0); v1 = tanhf(v1); }
                else          { v0 = fmaxf(v0, 0.f); v1 = fmaxf(v1, 0.f); }
                __nv_bfloat16 h0, l0, h1, l1;
                split_bf(v0, h0, l0); split_bf(v1, h1, l1);
                __nv_bfloat162 hh; hh.x = h0; hh.y = h1;
                __nv_bfloat162 ll; ll.x = l0; ll.y = l1;
                size_t idx = (size_t)r * HID + n0;
                *reinterpret_cast<__nv_bfloat162*>(&Ch[idx]) = hh;
                *reinterpret_cast<__nv_bfloat162*>(&Cl[idx]) = ll;
            }
        }
    }
}

// head2 inside persistent kernel: CTA handles 32 rows, warp 4 rows.
// Rh/Rl are cross-CTA mutable -> __ldcg (L2-coherent).
__device__ void head2_step(const __nv_bfloat16* Rh, const __nv_bfloat16* Rl,
                           const float* W2, const float* b2,
                           float* out, int t, int cta) {
    int warp = threadIdx.x >> 5;
    int lane = threadIdx.x & 31;
#pragma unroll
    for (int i = 0; i < 4; ++i) {
        int row = cta * 32 + warp * 4 + i;
        size_t base = (size_t)row * HID;
        float s0 = 0.f, s1 = 0.f;
#pragma unroll
        for (int j = 0; j < 8; ++j) {
            int k = j * 64 + lane * 2;
            unsigned uh = __ldcg((const unsigned*)(Rh + base + k));
            unsigned ul = __ldcg((const unsigned*)(Rl + base + k));
            __nv_bfloat162 h2 = *reinterpret_cast<__nv_bfloat162*>(&uh);
            __nv_bfloat162 l2 = *reinterpret_cast<__nv_bfloat162*>(&ul);
            float v0 = __bfloat162float(h2.x) + __bfloat162float(l2.x);
            float v1 = __bfloat162float(h2.y) + __bfloat162float(l2.y);
            s0 += v0 * W2[k] + v1 * W2[k + 1];
            s1 += v0 * W2[HID + k] + v1 * W2[HID + k + 1];
        }
#pragma unroll
        for (int off = 16; off; off >>= 1) {
            s0 += __shfl_down_sync(0xffffffffu, s0, off);
            s1 += __shfl_down_sync(0xffffffffu, s1, off);
        }
        if (lane == 0) {
            out[(size_t)row * (TDEC * 2) + t * 2 + 0] = tanhf(s0 + b2[0]);
            out[(size_t)row * (TDEC * 2) + t * 2 + 1] = tanhf(s1 + b2[1]);
        }
    }
}

// ---------------- persistent whole-network kernel ------------------------------
__global__ void __launch_bounds__(256, 1)
rnn_persistent(const __nv_bfloat16* __restrict__ Sh, const __nv_bfloat16* __restrict__ Sl,
               __nv_bfloat16* __restrict__ Hh, __nv_bfloat16* __restrict__ Hl,
               __nv_bfloat16* __restrict__ Rh, __nv_bfloat16* __restrict__ Rl,
               const __nv_bfloat16* __restrict__ Wh, const __nv_bfloat16* __restrict__ Wl,
               const float* __restrict__ bias,
               const float* __restrict__ headb1, const float* __restrict__ headW2,
               const float* __restrict__ headb2, float* __restrict__ out) {
    extern __shared__ char smc[];
    unsigned smraw = (unsigned)__cvta_generic_to_shared(smc);
    unsigned sm = (smraw + 1023u) & ~1023u;
    int cta = blockIdx.x;

    unsigned nbar = 0;
    int par = 0;

    auto hoff = [](int p, int l) { return (size_t)(p * 2 + l) * BH; };

    // ---- encoder: 33 steps ----
    for (int t = 0; t < SEQLEN; ++t) {
        int q = par ^ 1;
        gemm_step(Sh + (size_t)t * BH, Sl + (size_t)t * BH,
                  Hh + hoff(par, 0), Hl + hoff(par, 0),
                  Wh + 0 * MM, Wl + 0 * MM, Wh + 1 * MM, Wl + 1 * MM,
                  bias + 0 * HID, Hh + hoff(q, 0), Hl + hoff(q, 0), 1, 2, sm, cta);
        grid_sync(NCTA * ++nbar);
        gemm_step(Hh + hoff(q, 0), Hl + hoff(q, 0),
                  Hh + hoff(par, 1), Hl + hoff(par, 1),
                  Wh + 2 * MM, Wl + 2 * MM, Wh + 3 * MM, Wl + 3 * MM,
                  bias + 1 * HID, Hh + hoff(q, 1), Hl + hoff(q, 1), 1, 2, sm, cta);
        grid_sync(NCTA * ++nbar);
        par = q;
    }

    // ---- decoder: 60 steps ----
    for (int k = 0; k < TDEC; ++k) {
        int q = par ^ 1;
        gemm_step(Hh + hoff(par, 1), Hl + hoff(par, 1),
                  Hh + hoff(par, 0), Hl + hoff(par, 0),
                  Wh + 4 * MM, Wl + 4 * MM, Wh + 5 * MM, Wl + 5 * MM,
                  bias + 2 * HID, Hh + hoff(q, 0), Hl + hoff(q, 0), 1, 2, sm, cta);
        grid_sync(NCTA * ++nbar);
        gemm_step(Hh + hoff(q, 0), Hl + hoff(q, 0),
                  Hh + hoff(par, 1), Hl + hoff(par, 1),
                  Wh + 6 * MM, Wl + 6 * MM, Wh + 7 * MM, Wl + 7 * MM,
                  bias + 3 * HID, Hh + hoff(q, 1), Hl + hoff(q, 1), 1, 2, sm, cta);
        grid_sync(NCTA * ++nbar);
        gemm_step(Hh + hoff(q, 1), Hl + hoff(q, 1),
                  nullptr, nullptr,
                  Wh + 8 * MM, Wl + 8 * MM, nullptr, nullptr,
                  headb1, Rh, Rl, 2, 1, sm, cta);
        grid_sync(NCTA * ++nbar);
        head2_step(Rh, Rl, headW2, headb2, out, k, cta);
        par = q;
    }
}

// ---------------- launch ------------------------------------------------------
extern "C" void kernel_launch(void* const* d_in, const int* in_sizes, int n_in,
                              void* d_out, int out_size) {
    (void)in_sizes; (void)n_in; (void)out_size;
    const float* x      = (const float*)d_in[0];
    const float* emW    = (const float*)d_in[1];
    const float* emb    = (const float*)d_in[2];
    const float* evW    = (const float*)d_in[3];
    const float* evb    = (const float*)d_in[4];
    const float* encWih = (const float*)d_in[5];
    const float* encWhh = (const float*)d_in[6];
    const float* encbih = (const float*)d_in[7];
    const float* encbhh = (const float*)d_in[8];
    const float* decWih = (const float*)d_in[9];
    const float* decWhh = (const float*)d_in[10];
    const float* decbih = (const float*)d_in[11];
    const float* decbhh = (const float*)d_in[12];
    const float* headW1 = (const float*)d_in[13];
    const float* headb1 = (const float*)d_in[14];
    const float* headW2 = (const float*)d_in[15];
    const float* headb2 = (const float*)d_in[16];
    float* out = (float*)d_out;

    __nv_bfloat16 *Hh, *Hl, *Sh, *Sl, *Rh, *Rl, *Wh, *Wl;
    float *bias;
    cudaGetSymbolAddress((void**)&Hh, g_Hh);
    cudaGetSymbolAddress((void**)&Hl, g_Hl);
    cudaGetSymbolAddress((void**)&Sh, g_Sh);
    cudaGetSymbolAddress((void**)&Sl, g_Sl);
    cudaGetSymbolAddress((void**)&Rh, g_Rh);
    cudaGetSymbolAddress((void**)&Rl, g_Rl);
    cudaGetSymbolAddress((void**)&Wh, g_Wh);
    cudaGetSymbolAddress((void**)&Wl, g_Wl);
    cudaGetSymbolAddress((void**)&bias, g_bias);

    cudaFuncSetAttribute(rnn_persistent, cudaFuncAttributeMaxDynamicSharedMemorySize, SMEM_REQ);

    Ptr9 src;
    src.p[0] = encWih;        src.p[1] = encWhh;
    src.p[2] = encWih + MM;   src.p[3] = encWhh + MM;
    src.p[4] = decWih;        src.p[5] = decWhh;
    src.p[6] = decWih + MM;   src.p[7] = decWhh + MM;
    src.p[8] = headW1;

    wsplit_kernel<<<dim3(MM / 256, 9), 256>>>(src, Wh, Wl);
    bias_kernel<<<8, 256>>>(encbih, encbhh, decbih, decbhh, bias);   // also resets barrier
    zeroh_kernel<<<(2 * BH + 255) / 256, 256>>>(Hh, Hl, 2 * BH);
    embed_all_kernel<<<BATCH, HID>>>(x, emW, emb, evW, evb, Sh, Sl);

    rnn_persistent<<<NCTA, 256, SMEM_REQ>>>(Sh, Sl, Hh, Hl, Rh, Rl, Wh, Wl, bias,
                                            headb1, headW2, headb2, out);
}

// round 7
// speedup vs baseline: 2.2513x; 2.2513x over previous
#include <cuda_runtime.h>
#include <cuda_fp16.h>
#include <math.h>
#include <stdint.h>

// Problem constants
#define BATCH   4096
#define HID     512
#define CARNUM  32
#define SEQLEN  33
#define TDEC    60
#define XROW    198
#define BH      (BATCH * HID)
#define MM      (HID * HID)

// GEMM tiling: 128x128 CTA tile, BK=64 (128B rows, SW128), 8 warps (2M x 4N)
#define BM 128
#define BN 128
#define CHUNK_K 64
#define STAGES 3
#define TILE_BYTES 16384                 // 128 rows x 128B
#define STAGE_BYTES (2 * TILE_BYTES)     // A, B
#define SMEM_REQ (1024 + STAGES * STAGE_BYTES)

#define SW128(o) ((o) ^ (((o) >> 3) & 0x70))

// ---------------- device globals ----------------------------------------------
__device__ __align__(128) __half g_H[2 * 2 * BH];     // [parity][layer][B*H]
__device__ __align__(128) __half g_S[SEQLEN * BH];    // embedded seq
__device__ __align__(128) __half g_R[BH];             // head hidden (relu)
__device__ __align__(128) __half g_W[9 * MM];         // fp16 weights, [n][k] layout
__device__ float g_bias[4 * HID];

struct Ptr9 { const float* p[9]; };

// ---------------- helpers -----------------------------------------------------
__device__ __forceinline__ void cp16(unsigned dst, const void* src) {
    asm volatile("cp.async.cg.shared.global [%0], [%1], 16;" :: "r"(dst), "l"(src) : "memory");
}

__device__ __forceinline__ void ldsm4(unsigned* r, unsigned addr) {
    asm volatile("ldmatrix.sync.aligned.m8n8.x4.shared.b16 {%0,%1,%2,%3}, [%4];"
                 : "=r"(r[0]), "=r"(r[1]), "=r"(r[2]), "=r"(r[3]) : "r"(addr));
}

__device__ __forceinline__ void mma16816(float* c, const unsigned* a, const unsigned* b) {
    asm volatile(
        "mma.sync.aligned.m16n8k16.row.col.f32.f16.f16.f32 "
        "{%0,%1,%2,%3}, {%4,%5,%6,%7}, {%8,%9}, {%0,%1,%2,%3};"
        : "+f"(c[0]), "+f"(c[1]), "+f"(c[2]), "+f"(c[3])
        : "r"(a[0]), "r"(a[1]), "r"(a[2]), "r"(a[3]), "r"(b[0]), "r"(b[1]));
}

// ---------------- prep kernels ------------------------------------------------
__global__ void wsplit_kernel(Ptr9 s, __half* __restrict__ W) {
    int m = blockIdx.y;
    int i = blockIdx.x * blockDim.x + threadIdx.x;
    W[(size_t)m * MM + i] = __float2half(s.p[m][i]);
}

__global__ void bias_kernel(const float* __restrict__ ebih, const float* __restrict__ ebhh,
                            const float* __restrict__ dbih, const float* __restrict__ dbhh,
                            float* __restrict__ out) {
    int i = blockIdx.x * blockDim.x + threadIdx.x;
    if (i < 1024)      out[i] = ebih[i] + ebhh[i];
    else if (i < 2048) out[i] = dbih[i - 1024] + dbhh[i - 1024];
}

__global__ void zeroh_kernel(__half* __restrict__ a, int n) {
    int i = blockIdx.x * blockDim.x + threadIdx.x;
    if (i < n) a[i] = __float2half(0.f);
}

// one block per batch row; all 33 timesteps
__global__ void embed_all_kernel(const float* __restrict__ x,
                                 const float* __restrict__ Wm, const float* __restrict__ bm,
                                 const float* __restrict__ Wv, const float* __restrict__ bv,
                                 __half* __restrict__ S) {
    __shared__ float sx[XROW];
    int b = blockIdx.x, e = threadIdx.x;
    if (e < XROW) sx[e] = x[(size_t)b * XROW + e];
    __syncthreads();
    float wv[6], wm[6];
#pragma unroll
    for (int j = 0; j < 6; ++j) { wv[j] = Wv[e * 6 + j]; wm[j] = Wm[e * 6 + j]; }
    float bve = bv[e], bme = bm[e];
    for (int t = 0; t < CARNUM; ++t) {
        float s = bve;
#pragma unroll
        for (int j = 0; j < 6; ++j) s += sx[6 + 6 * t + j] * wv[j];
        S[((size_t)t * BATCH + b) * HID + e] = __float2half(tanhf(s));
    }
    {
        float s = bme;
#pragma unroll
        for (int j = 0; j < 6; ++j) s += sx[j] * wm[j];
        S[((size_t)CARNUM * BATCH + b) * HID + e] = __float2half(tanhf(s));
    }
}

// ---------------- fp16 HMMA GEMM (ldmatrix + 3-stage cp.async) -----------------
// C[M,512] = act( sum_pairs A@W^T + bias ), A row-major [m][k], W [n][k]
__global__ void __launch_bounds__(256, 1)
gemm_hmma(const __half* __restrict__ A1, const __half* __restrict__ A2,
          const __half* __restrict__ B1, const __half* __restrict__ B2,
          const float* __restrict__ bias, __half* __restrict__ C,
          int act, int npairs) {
    extern __shared__ char smc[];
    unsigned smraw = (unsigned)__cvta_generic_to_shared(smc);
    unsigned sm = (smraw + 1023u) & ~1023u;

    int tid  = threadIdx.x;
    int warp = tid >> 5;
    int lane = tid & 31;
    int wm = warp >> 2;        // 0..1  (M)
    int wn = warp & 3;         // 0..3  (N)
    int li  = lane & 7;
    int grp = lane >> 3;
    int mBase = blockIdx.y * BM;
    int nBase = blockIdx.x * BN;
    int NT = npairs * (HID / CHUNK_K);      // 8 or 16

    float acc[4][4][4];
#pragma unroll
    for (int mt = 0; mt < 4; ++mt)
#pragma unroll
        for (int nt = 0; nt < 4; ++nt)
#pragma unroll
            for (int c = 0; c < 4; ++c) acc[mt][nt][c] = 0.f;

    auto prefetch = [&](int chunk) {
        int buf = chunk % STAGES;
        int pair = chunk >> 3;
        int k0 = (chunk & 7) * CHUNK_K;
        const __half* PA = pair ? A2 : A1;
        const __half* PB = pair ? B2 : B1;
        unsigned sb = sm + buf * STAGE_BYTES;
#pragma unroll
        for (int i = 0; i < 8; ++i) {
            int cid = tid + 256 * i;
            int arr = cid >> 10;               // 0 = A, 1 = B
            int r   = (cid >> 3) & 127;
            int seg = cid & 7;
            const __half* p = arr ? PB : PA;
            int rb = (arr ? nBase : mBase) + r;
            const void* src = p + (size_t)rb * HID + k0 + seg * 8;
            unsigned dst = sb + arr * TILE_BYTES + SW128(r * 128 + seg * 16);
            cp16(dst, src);
        }
        asm volatile("cp.async.commit_group;" ::: "memory");
    };

    prefetch(0);
    if (NT > 1) prefetch(1);

    for (int c = 0; c < NT; ++c) {
        if (c + 2 < NT) prefetch(c + 2);
        if (c + 2 < NT)      asm volatile("cp.async.wait_group 2;" ::: "memory");
        else if (c + 1 < NT) asm volatile("cp.async.wait_group 1;" ::: "memory");
        else                 asm volatile("cp.async.wait_group 0;" ::: "memory");
        __syncthreads();

        unsigned sb = sm + (c % STAGES) * STAGE_BYTES;
        unsigned sA = sb;
        unsigned sB = sb + TILE_BYTES;

#pragma unroll
        for (int kq = 0; kq < 4; ++kq) {
            unsigned a[4][4];
#pragma unroll
            for (int mt = 0; mt < 4; ++mt) {
                int r = wm * 64 + mt * 16 + ((grp & 1) << 3) + li;
                int cc = kq * 32 + ((grp & 2) << 3);
                unsigned off = (unsigned)(r * 128 + (cc ^ (li << 4)));
                ldsm4(a[mt], sA + off);
            }
            unsigned b[2][4];
#pragma unroll
            for (int nb = 0; nb < 2; ++nb) {
                int n = wn * 32 + nb * 16 + ((grp & 2) << 2) + li;
                int cc = kq * 32 + ((grp & 1) << 4);
                unsigned off = (unsigned)(n * 128 + (cc ^ (li << 4)));
                ldsm4(b[nb], sB + off);
            }
#pragma unroll
            for (int mt = 0; mt < 4; ++mt)
#pragma unroll
                for (int nt = 0; nt < 4; ++nt)
                    mma16816(acc[mt][nt], a[mt], &b[nt >> 1][(nt & 1) * 2]);
        }
        __syncthreads();
    }

    // ---- epilogue: bias + activation, fp16 store ----
#pragma unroll
    for (int mt = 0; mt < 4; ++mt) {
        int r0 = mBase + wm * 64 + mt * 16 + (lane >> 2);
#pragma unroll
        for (int nt = 0; nt < 4; ++nt) {
            int n0 = nBase + wn * 32 + nt * 8 + 2 * (lane & 3);
            float b0 = bias[n0], b1 = bias[n0 + 1];
#pragma unroll
            for (int half_ = 0; half_ < 2; ++half_) {
                int r = r0 + half_ * 8;
                float v0 = acc[mt][nt][half_ * 2 + 0] + b0;
                float v1 = acc[mt][nt][half_ * 2 + 1] + b1;
                if (act == 1) { v0 = tanhf(v0); v1 = tanhf(v1); }
                else          { v0 = fmaxf(v0, 0.f); v1 = fmaxf(v1, 0.f); }
                __half2 hv; hv.x = __float2half(v0); hv.y = __float2half(v1);
                *reinterpret_cast<__half2*>(&C[(size_t)r * HID + n0]) = hv;
            }
        }
    }
}

// out[b, t, :] = tanh(r @ W2^T + b2) — one warp per batch row
__global__ void head2_kernel(const __half* __restrict__ rr,
                             const float* __restrict__ W2,
                             const float* __restrict__ b2, float* __restrict__ out, int t) {
    int warp = (blockIdx.x * blockDim.x + threadIdx.x) >> 5;
    int lane = threadIdx.x & 31;
    if (warp >= BATCH) return;
    size_t base = (size_t)warp * HID;
    float s0 = 0.f, s1 = 0.f;
#pragma unroll
    for (int j = 0; j < 8; ++j) {
        int k = j * 64 + lane * 2;
        __half2 v2 = *reinterpret_cast<const __half2*>(rr + base + k);
        float v0 = __half2float(v2.x), v1 = __half2float(v2.y);
        s0 += v0 * W2[k] + v1 * W2[k + 1];
        s1 += v0 * W2[HID + k] + v1 * W2[HID + k + 1];
    }
#pragma unroll
    for (int off = 16; off; off >>= 1) {
        s0 += __shfl_down_sync(0xffffffffu, s0, off);
        s1 += __shfl_down_sync(0xffffffffu, s1, off);
    }
    if (lane == 0) {
        out[(size_t)warp * (TDEC * 2) + t * 2 + 0] = tanhf(s0 + b2[0]);
        out[(size_t)warp * (TDEC * 2) + t * 2 + 1] = tanhf(s1 + b2[1]);
    }
}

// ---------------- launch ------------------------------------------------------
extern "C" void kernel_launch(void* const* d_in, const int* in_sizes, int n_in,
                              void* d_out, int out_size) {
    (void)in_sizes; (void)n_in; (void)out_size;
    const float* x      = (const float*)d_in[0];
    const float* emW    = (const float*)d_in[1];
    const float* emb    = (const float*)d_in[2];
    const float* evW    = (const float*)d_in[3];
    const float* evb    = (const float*)d_in[4];
    const float* encWih = (const float*)d_in[5];
    const float* encWhh = (const float*)d_in[6];
    const float* encbih = (const float*)d_in[7];
    const float* encbhh = (const float*)d_in[8];
    const float* decWih = (const float*)d_in[9];
    const float* decWhh = (const float*)d_in[10];
    const float* decbih = (const float*)d_in[11];
    const float* decbhh = (const float*)d_in[12];
    const float* headW1 = (const float*)d_in[13];
    const float* headb1 = (const float*)d_in[14];
    const float* headW2 = (const float*)d_in[15];
    const float* headb2 = (const float*)d_in[16];
    float* out = (float*)d_out;

    __half *H, *S, *R, *W;
    float *bias;
    cudaGetSymbolAddress((void**)&H, g_H);
    cudaGetSymbolAddress((void**)&S, g_S);
    cudaGetSymbolAddress((void**)&R, g_R);
    cudaGetSymbolAddress((void**)&W, g_W);
    cudaGetSymbolAddress((void**)&bias, g_bias);

    cudaFuncSetAttribute(gemm_hmma, cudaFuncAttributeMaxDynamicSharedMemorySize, SMEM_REQ);

    Ptr9 src;
    src.p[0] = encWih;        src.p[1] = encWhh;
    src.p[2] = encWih + MM;   src.p[3] = encWhh + MM;
    src.p[4] = decWih;        src.p[5] = decWhh;
    src.p[6] = decWih + MM;   src.p[7] = decWhh + MM;
    src.p[8] = headW1;

    wsplit_kernel<<<dim3(MM / 256, 9), 256>>>(src, W);
    bias_kernel<<<8, 256>>>(encbih, encbhh, decbih, decbhh, bias);
    zeroh_kernel<<<(2 * BH + 255) / 256, 256>>>(H, 2 * BH);    // parity-0 region
    embed_all_kernel<<<BATCH, HID>>>(x, emW, emb, evW, evb, S);

    auto hOff = [](int p, int l) { return (size_t)(p * 2 + l) * BH; };
    dim3 ggrid(HID / BN, BATCH / BM);   // (4, 32) = 128 CTAs
    int s = 0;

    // ---- encoder ----
    for (int t = 0; t < SEQLEN; ++t) {
        int p = s & 1, q = p ^ 1;
        gemm_hmma<<<ggrid, 256, SMEM_REQ>>>(
            S + (size_t)t * BH, H + hOff(p, 0),
            W + 0 * MM, W + 1 * MM,
            bias + 0 * HID, H + hOff(q, 0), 1, 2);
        gemm_hmma<<<ggrid, 256, SMEM_REQ>>>(
            H + hOff(q, 0), H + hOff(p, 1),
            W + 2 * MM, W + 3 * MM,
            bias + 1 * HID, H + hOff(q, 1), 1, 2);
        s++;
    }

    // ---- decoder ----
    for (int k = 0; k < TDEC; ++k) {
        int p = s & 1, q = p ^ 1;
        gemm_hmma<<<ggrid, 256, SMEM_REQ>>>(
            H + hOff(p, 1), H + hOff(p, 0),
            W + 4 * MM, W + 5 * MM,
            bias + 2 * HID, H + hOff(q, 0), 1, 2);
        gemm_hmma<<<ggrid, 256, SMEM_REQ>>>(
            H + hOff(q, 0), H + hOff(p, 1),
            W + 6 * MM, W + 7 * MM,
            bias + 3 * HID, H + hOff(q, 1), 1, 2);
        gemm_hmma<<<ggrid, 256, SMEM_REQ>>>(
            H + hOff(q, 1), nullptr,
            W + 8 * MM, nullptr,
            headb1, R, 2, 1);
        head2_kernel<<<512, 256>>>(R, headW2, headb2, out, k);
        s++;
    }
}